// round 6
// baseline (speedup 1.0000x reference)
#include <cuda_runtime.h>
#include <math.h>
#include <stdint.h>

typedef unsigned long long u64;

__device__ __forceinline__ u64 pk(float a, float b) {
    u64 r; asm("mov.b64 %0,{%1,%2};" : "=l"(r) : "f"(a), "f"(b)); return r;
}
__device__ __forceinline__ void fma2(u64& d, u64 a, u64 b) {
    asm("fma.rn.f32x2 %0, %1, %2, %0;" : "+l"(d) : "l"(a), "l"(b));
}
__device__ __forceinline__ float2 unpk(u64 x) {
    float2 f; asm("mov.b64 {%0,%1},%2;" : "=f"(f.x), "=f"(f.y) : "l"(x)); return f;
}
__device__ __forceinline__ uint32_t saddr(const void* p) {
    uint32_t a;
    asm("{.reg .u64 t; cvta.to.shared.u64 t,%1; cvt.u32.u64 %0,t;}" : "=r"(a) : "l"(p));
    return a;
}
__device__ __forceinline__ void cp4(uint32_t dst, const void* src, bool pred) {
    asm volatile("cp.async.ca.shared.global [%0], [%1], 4, %2;"
                 :: "r"(dst), "l"(src), "r"(pred ? 4u : 0u));
}
__device__ __forceinline__ void cp_commit() { asm volatile("cp.async.commit_group;"); }
__device__ __forceinline__ void cp_wait1()  { asm volatile("cp.async.wait_group 1;"); }

// ---------------- scratch ----------------
__device__ float g_h1[67108864];   // [32,128,128,128]
__device__ float g_h2[8388608];    // [32,64,64,64]
__device__ float g_z [8388608];    // NHWC [32,64,64][64]
__device__ float g_q [8388608];    // NCHW [32,64,64,64]
__device__ float g_g1[67108864];   // [32,128,128,128]
__device__ float g_g2[134217728];  // [32,64,256,256]
__device__ int    g_idx[131072];
__device__ float  g_ee[512];
__device__ float  g_counts[512];
__device__ double g_loss_sum;

__global__ void k_init() {
    int t = threadIdx.x;
    if (t < 512) g_counts[t] = 0.f;
    if (t == 0) g_loss_sum = 0.0;
}

// conv1: x[32,1,256,256] -> h1[32,128,128,128], 4x4 s2 p1, relu
__global__ void __launch_bounds__(128) k_conv1(const float* __restrict__ x,
                                               const float* __restrict__ w,
                                               const float* __restrict__ b) {
    __shared__ float sW[2048];
    __shared__ float sB[128];
    int ox = threadIdx.x, oy = blockIdx.x, n = blockIdx.y;
    for (int i = threadIdx.x; i < 2048; i += 128) sW[i] = w[i];
    sB[threadIdx.x] = b[threadIdx.x];
    __syncthreads();
    float p[16];
    const float* xb = x + (size_t)n * 65536;
#pragma unroll
    for (int ky = 0; ky < 4; ky++) {
        int iy = oy * 2 - 1 + ky;
#pragma unroll
        for (int kx = 0; kx < 4; kx++) {
            int ix = ox * 2 - 1 + kx;
            p[ky * 4 + kx] = (iy >= 0 && iy < 256 && ix >= 0 && ix < 256) ? xb[iy * 256 + ix] : 0.f;
        }
    }
    u64 p2[8];
#pragma unroll
    for (int u = 0; u < 8; u++) p2[u] = pk(p[2 * u], p[2 * u + 1]);
    float* ob = g_h1 + (size_t)n * 2097152 + (size_t)oy * 128 + ox;
    for (int c = 0; c < 128; c++) {
        const ulonglong2* wp = (const ulonglong2*)&sW[c * 16];
        u64 a2 = 0ull, b2 = 0ull;
#pragma unroll
        for (int u = 0; u < 4; u++) {
            ulonglong2 t = wp[u];
            fma2(a2, p2[2 * u], t.x);
            fma2(b2, p2[2 * u + 1], t.y);
        }
        float2 fa = unpk(a2), fb = unpk(b2);
        ob[(size_t)c * 16384] = fmaxf((fa.x + fa.y) + (fb.x + fb.y) + sB[c], 0.f);
    }
}

// conv2: h1 -> h2[32,64,64,64], 128ic 4x4 s2 p1, relu.
// tile 32x*4y*64oc, thread: 2x * 16oc, 3 CTA/SM target.
__global__ void __launch_bounds__(256, 3) k_conv2(const float* __restrict__ w,
                                                  const float* __restrict__ b) {
    extern __shared__ float sm2[];
    float* sInD = sm2;              // 2 x 2640 (4ic*10*66)
    float* sWD  = sm2 + 2 * 2640;   // 2 x 4096
    int tid = threadIdx.x;
    int tx = tid & 15, ty = (tid >> 4) & 3, tz = tid >> 6;
    int n = blockIdx.z, oy0 = blockIdx.y * 4, ox0 = blockIdx.x * 32;
    const float* inb = g_h1 + (size_t)n * 2097152;
    u64 acc2[2][8] = {};
    const int IY0 = oy0 * 2 - 1, IX0 = ox0 * 2 - 1;

    auto fill = [&](int ic0, int buf) {
        float* dI = sInD + buf * 2640;
        for (int i = tid; i < 2640; i += 256) {
            int j = i / 660, rem = i - j * 660, yy = rem / 66, xx = rem - yy * 66;
            int iy = IY0 + yy, ix = IX0 + xx;
            bool pr = (iy >= 0 && iy < 128 && ix >= 0 && ix < 128);
            const float* sp = pr ? &inb[((size_t)(ic0 + j) * 128 + iy) * 128 + ix] : inb;
            cp4(saddr(dI + i), sp, pr);
        }
        float* dW = sWD + buf * 4096;
        for (int i = tid; i < 4096; i += 256) {
            int j = i >> 10, rem = i & 1023, t = rem >> 6, oc = rem & 63;
            cp4(saddr(dW + i), &w[((size_t)(oc << 7) + ic0 + j) * 16 + t], true);
        }
    };

    fill(0, 0);
    cp_commit();
    for (int c = 0; c < 32; c++) {
        int buf = c & 1;
        if (c + 1 < 32) fill((c + 1) * 4, (c + 1) & 1);
        cp_commit();
        cp_wait1();
        __syncthreads();
        const float* pI = sInD + buf * 2640;
        const float* pW = sWD + buf * 4096;
#pragma unroll
        for (int j = 0; j < 4; j++) {
#pragma unroll
            for (int ky = 0; ky < 4; ky++) {
                const float* rp = &pI[(j * 10 + ty * 2 + ky) * 66 + tx * 4];
                float v[6];
#pragma unroll
                for (int cc = 0; cc < 6; cc++) v[cc] = rp[cc];
#pragma unroll
                for (int kx = 0; kx < 4; kx++) {
                    u64 vv0 = pk(v[kx], v[kx]);
                    u64 vv1 = pk(v[kx + 2], v[kx + 2]);
                    const ulonglong2* wp = (const ulonglong2*)&pW[((j << 4) + (ky << 2) + kx) * 64 + tz * 16];
                    u64 wv[8];
#pragma unroll
                    for (int u = 0; u < 4; u++) {
                        ulonglong2 t = wp[u];
                        wv[2 * u] = t.x; wv[2 * u + 1] = t.y;
                    }
#pragma unroll
                    for (int o = 0; o < 8; o++) {
                        fma2(acc2[0][o], vv0, wv[o]);
                        fma2(acc2[1][o], vv1, wv[o]);
                    }
                }
            }
        }
        __syncthreads();
    }
    int oy = oy0 + ty;
    int oxb = ox0 + 2 * tx;
#pragma unroll
    for (int o = 0; o < 8; o++) {
        int oce = tz * 16 + 2 * o;
        float be = b[oce], bo = b[oce + 1];
        float2 a0 = unpk(acc2[0][o]), a1 = unpk(acc2[1][o]);
        float2 re, ro;
        re.x = fmaxf(a0.x + be, 0.f); re.y = fmaxf(a1.x + be, 0.f);
        ro.x = fmaxf(a0.y + bo, 0.f); ro.y = fmaxf(a1.y + bo, 0.f);
        *(float2*)&g_h2[(((size_t)n * 64 + oce) * 64 + oy) * 64 + oxb] = re;
        *(float2*)&g_h2[(((size_t)n * 64 + oce + 1) * 64 + oy) * 64 + oxb] = ro;
    }
}

// conv3: h2 -> z NHWC, 64ic 3x3 s1 p1. tile 32x*4y*64oc, thread 2x*16oc.
__global__ void __launch_bounds__(256, 3) k_conv3(const float* __restrict__ w,
                                                  const float* __restrict__ b) {
    extern __shared__ float sm3[];
    float* sInD = sm3;              // 2 x 1632 (8ic*6*34)
    float* sWD  = sm3 + 2 * 1632;   // 2 x 4608
    int tid = threadIdx.x;
    int tx = tid & 15, ty = (tid >> 4) & 3, tz = tid >> 6;
    int n = blockIdx.z, oy0 = blockIdx.y * 4, ox0 = blockIdx.x * 32;
    const float* inb = g_h2 + (size_t)n * 262144;
    u64 acc2[2][8] = {};

    auto fill = [&](int ic0, int buf) {
        float* dI = sInD + buf * 1632;
        for (int i = tid; i < 1632; i += 256) {
            int j = i / 204, rem = i - j * 204, yy = rem / 34, xx = rem - yy * 34;
            int iy = oy0 - 1 + yy, ix = ox0 - 1 + xx;
            bool pr = (iy >= 0 && iy < 64 && ix >= 0 && ix < 64);
            const float* sp = pr ? &inb[((size_t)(ic0 + j) * 64 + iy) * 64 + ix] : inb;
            cp4(saddr(dI + i), sp, pr);
        }
        float* dW = sWD + buf * 4608;
        for (int i = tid; i < 4608; i += 256) {
            int j = i / 576, rem = i - j * 576, t = rem >> 6, oc = rem & 63;
            cp4(saddr(dW + i), &w[((size_t)oc * 64 + ic0 + j) * 9 + t], true);
        }
    };

    fill(0, 0);
    cp_commit();
    for (int c = 0; c < 8; c++) {
        int buf = c & 1;
        if (c + 1 < 8) fill((c + 1) * 8, (c + 1) & 1);
        cp_commit();
        cp_wait1();
        __syncthreads();
        const float* pI = sInD + buf * 1632;
        const float* pW = sWD + buf * 4608;
#pragma unroll
        for (int j = 0; j < 8; j++) {
#pragma unroll
            for (int ky = 0; ky < 3; ky++) {
                const float* rp = &pI[(j * 6 + ty + ky) * 34 + tx * 2];
                float v[4];
#pragma unroll
                for (int cc = 0; cc < 4; cc++) v[cc] = rp[cc];
#pragma unroll
                for (int kx = 0; kx < 3; kx++) {
                    u64 vv0 = pk(v[kx], v[kx]);
                    u64 vv1 = pk(v[kx + 1], v[kx + 1]);
                    const ulonglong2* wp = (const ulonglong2*)&pW[(j * 9 + ky * 3 + kx) * 64 + tz * 16];
                    u64 wv[8];
#pragma unroll
                    for (int u = 0; u < 4; u++) {
                        ulonglong2 t = wp[u];
                        wv[2 * u] = t.x; wv[2 * u + 1] = t.y;
                    }
#pragma unroll
                    for (int o = 0; o < 8; o++) {
                        fma2(acc2[0][o], vv0, wv[o]);
                        fma2(acc2[1][o], vv1, wv[o]);
                    }
                }
            }
        }
        __syncthreads();
    }
    int oy = oy0 + ty;
    float bb[16];
#pragma unroll
    for (int i = 0; i < 16; i++) bb[i] = b[tz * 16 + i];
#pragma unroll
    for (int q = 0; q < 2; q++) {
        int ox = ox0 + 2 * tx + q;
        float* zp = g_z + (((size_t)n * 64 + oy) * 64 + ox) * 64 + tz * 16;
#pragma unroll
        for (int o = 0; o < 8; o++) {
            float2 e = unpk(acc2[q][o]);
            float2 r; r.x = e.x + bb[2 * o]; r.y = e.y + bb[2 * o + 1];
            ((float2*)zp)[o] = r;
        }
    }
}

__global__ void k_ee(const float* __restrict__ emb) {
    int k = threadIdx.x;
    float s = 0.f;
    for (int d = 0; d < 64; d++) { float e = emb[d * 512 + k]; s += e * e; }
    g_ee[k] = s;
}

// VQ argmin
__global__ void __launch_bounds__(256) k_vq(const float* __restrict__ emb) {
    __shared__ float sE[64 * 68];
    __shared__ float sEE[64];
    int tid = threadIdx.x;
    int row = blockIdx.x * 256 + tid;
    u64 zr2[32];
    const float4* zp = (const float4*)(g_z + (size_t)row * 64);
#pragma unroll
    for (int j = 0; j < 16; j++) {
        float4 t = zp[j];
        zr2[2 * j]     = pk(t.x, t.y);
        zr2[2 * j + 1] = pk(t.z, t.w);
    }
    float best = 3.4e38f;
    int bi = 0;
    for (int kc = 0; kc < 512; kc += 64) {
        __syncthreads();
        for (int i = tid; i < 4096; i += 256) {
            int d = i >> 6, k = i & 63;
            sE[k * 68 + d] = emb[d * 512 + kc + k];
        }
        if (tid < 64) sEE[tid] = g_ee[kc + tid];
        __syncthreads();
        for (int k = 0; k < 64; k++) {
            const ulonglong2* ep = (const ulonglong2*)&sE[k * 68];
            u64 sa = 0ull, sb = 0ull;
#pragma unroll
            for (int jj = 0; jj < 16; jj++) {
                ulonglong2 e = ep[jj];
                fma2(sa, zr2[2 * jj], e.x);
                fma2(sb, zr2[2 * jj + 1], e.y);
            }
            float2 fa = unpk(sa), fb = unpk(sb);
            float dd = sEE[k] - 2.f * ((fa.x + fa.y) + (fb.x + fb.y));
            if (dd < best) { best = dd; bi = kc + k; }
        }
    }
    g_idx[row] = bi;
    atomicAdd(&g_counts[bi], 1.f);
}

// gather codes + loss + NCHW transpose (128 rows/block)
__global__ void __launch_bounds__(256) k_gather(const float* __restrict__ emb) {
    __shared__ float sQ[8192];
    __shared__ float sRed[256];
    int tid = threadIdx.x;
    int r0 = blockIdx.x * 128;
    int rl = tid & 127, half = tid >> 7;
    int r = r0 + rl;
    int id = g_idx[r];
    const float4* z4 = (const float4*)(g_z + (size_t)r * 64 + half * 32);
    float ls = 0.f;
#pragma unroll
    for (int jj = 0; jj < 8; jj++) {
        float4 zv = z4[jj];
        int d = half * 32 + jj * 4;
        float e0 = emb[(d+0)*512 + id];
        float e1 = emb[(d+1)*512 + id];
        float e2 = emb[(d+2)*512 + id];
        float e3 = emb[(d+3)*512 + id];
        float d0=e0-zv.x, d1=e1-zv.y, d2=e2-zv.z, d3=e3-zv.w;
        ls += d0*d0 + d1*d1 + d2*d2 + d3*d3;
        sQ[(d+0)*128 + rl] = e0;
        sQ[(d+1)*128 + rl] = e1;
        sQ[(d+2)*128 + rl] = e2;
        sQ[(d+3)*128 + rl] = e3;
    }
    __syncthreads();
    int n = r0 >> 12;
    int y0x = r0 & 4095;
    float* qb = g_q + ((size_t)n << 18) + y0x;
    for (int i = tid; i < 8192; i += 256) {
        int d = i >> 7, rl2 = i & 127;
        qb[(size_t)d * 4096 + rl2] = sQ[i];
    }
    sRed[tid] = ls;
    __syncthreads();
    for (int s = 128; s > 0; s >>= 1) {
        if (tid < s) sRed[tid] += sRed[tid + s];
        __syncthreads();
    }
    if (tid == 0) atomicAdd(&g_loss_sum, (double)sRed[0]);
}

__global__ void k_finalize(float* __restrict__ out, int out_size) {
    __shared__ float red[512];
    int t = threadIdx.x;
    float c = g_counts[t];
    float p = c * (1.f / 131072.f);
    red[t] = p * logf(p + 1e-10f);
    __syncthreads();
    for (int s = 256; s > 0; s >>= 1) {
        if (t < s) red[t] += red[t + s];
        __syncthreads();
    }
    if (t == 0) {
        out[out_size - 1] = expf(-red[0]);
        out[0] = (float)(g_loss_sum * (1.25 / 8388608.0));
    }
}

// transposed conv 3x3 s2 p1 op1, relu.
// thread = one input site (uy,ux) -> 2x2 output quad, 8 oc. Exact 9 taps/ic.
__global__ void __launch_bounds__(256, 3) k_convT(const float* __restrict__ in,
                                                  const float* __restrict__ w,
                                                  const float* __restrict__ b,
                                                  float* __restrict__ out,
                                                  int IC, int OC, int INS, int OUTS) {
    __shared__ float sIn[2][2376];   // 8ic * 9 * 33
    __shared__ float sW[2][576];
    int tid = threadIdx.x;
    int tx = tid & 31, ty = tid >> 5;   // ux, uy
    int ocChunks = OC >> 3;
    int z = blockIdx.z;
    int oc0 = (z % ocChunks) * 8;
    int n = z / ocChunks;
    int ux0 = blockIdx.x * 32, uy0 = blockIdx.y * 8;
    const float* inb = in + (size_t)n * IC * INS * INS;
    u64 acc2[2][2][4] = {};   // [dy][dx][ocpair]
    int K = IC >> 3;

    auto fill = [&](int ic0, int buf) {
        for (int i = tid; i < 2376; i += 256) {
            int j = i / 297, rem = i - j * 297, yy = rem / 33, xx = rem - yy * 33;
            int iy = uy0 + yy, ix = ux0 + xx;
            bool pr = (iy < INS && ix < INS);
            const float* sp = pr ? &inb[((size_t)(ic0 + j) * INS + iy) * INS + ix] : inb;
            cp4(saddr(&sIn[buf][i]), sp, pr);
        }
        for (int i = tid; i < 576; i += 256) {
            int j = i / 72, rem = i - j * 72, tap = rem >> 3, o = rem & 7;
            cp4(saddr(&sW[buf][i]), &w[((size_t)(ic0 + j) * OC + oc0 + o) * 9 + tap], true);
        }
    };

    fill(0, 0);
    cp_commit();
    for (int c = 0; c < K; c++) {
        int buf = c & 1;
        if (c + 1 < K) fill((c + 1) * 8, (c + 1) & 1);
        cp_commit();
        cp_wait1();
        __syncthreads();
#pragma unroll
        for (int j = 0; j < 8; j++) {
            const float* r0 = &sIn[buf][(j * 9 + ty) * 33 + tx];
            float i00 = r0[0], i01 = r0[1], i10 = r0[33], i11 = r0[34];
            u64 p00 = pk(i00, i00), p01 = pk(i01, i01), p10 = pk(i10, i10), p11 = pk(i11, i11);
            const float* wj = &sW[buf][j * 72];
            // tap(ky,kx) -> wv[4] at wj + (ky*3+kx)*8
#pragma unroll
            for (int tap = 0; tap < 9; tap++) {
                int ky = tap / 3, kx = tap - ky * 3;
                const ulonglong2* wp = (const ulonglong2*)&wj[tap * 8];
                ulonglong2 t0 = wp[0], t1 = wp[1];
                u64 wv[4] = {t0.x, t0.y, t1.x, t1.y};
                // select source + dest by tap
                u64 src; int dy, dx;
                if (ky == 1) { dy = 0; src = (kx == 1) ? p00 : (kx == 2 ? p00 : p01); }
                else if (ky == 2) { dy = 1; src = (kx == 0) ? p01 : p00; }
                else { dy = 1; src = (kx == 0) ? p11 : (kx == 1 ? p10 : p10); }
                if (kx == 1) dx = 0;
                else dx = 1;
                // correction: ky==1,kx==1 -> (0,0) i00 ; ky==1,kx==2 -> (0,1) i00 ; ky==1,kx==0 -> (0,1) i01
                // ky==2,kx==1 -> (1,0) i00 ; ky==2,kx==2 -> (1,1) i00 ; ky==2,kx==0 -> (1,1) i01
                // ky==0,kx==1 -> (1,0) i10 ; ky==0,kx==2 -> (1,1) i10 ; ky==0,kx==0 -> (1,1) i11
#pragma unroll
                for (int op = 0; op < 4; op++) fma2(acc2[dy][dx][op], src, wv[op]);
            }
        }
        __syncthreads();
    }
    int oyb = 2 * (uy0 + ty);
    int oxb = 2 * (ux0 + tx);
#pragma unroll
    for (int op = 0; op < 4; op++) {
        int oce = oc0 + 2 * op;
        float be = b[oce], bo = b[oce + 1];
#pragma unroll
        for (int dy = 0; dy < 2; dy++) {
            int oy = oyb + dy;
            float2 s0 = unpk(acc2[dy][0][op]), s1 = unpk(acc2[dy][1][op]);
            float2 re, ro;
            re.x = fmaxf(s0.x + be, 0.f); re.y = fmaxf(s1.x + be, 0.f);
            ro.x = fmaxf(s0.y + bo, 0.f); ro.y = fmaxf(s1.y + bo, 0.f);
            *(float2*)&out[(((size_t)n * OC + oce) * OUTS + oy) * OUTS + oxb] = re;
            *(float2*)&out[(((size_t)n * OC + oce + 1) * OUTS + oy) * OUTS + oxb] = ro;
        }
    }
}

// convT3: g2 -> recon[32,1,256,256]: conv with flipped kernel, pad1. cp.async 2-stage.
__global__ void __launch_bounds__(256) k_convT3(const float* __restrict__ w,
                                                const float* __restrict__ b,
                                                float* __restrict__ out) {
    extern __shared__ float smT[];
    float* sInD = smT;               // 2 x 9504 (8*18*66)
    float* sW   = smT + 2 * 9504;    // 576
    int tid = threadIdx.x;
    int tx = tid & 15, ty = tid >> 4;
    int n = blockIdx.z;
    int y0 = blockIdx.y * 16, x0 = blockIdx.x * 64;
    for (int i = tid; i < 576; i += 256) {
        int ic = i / 9, t = i - ic * 9;
        sW[i] = w[ic * 9 + (8 - t)];
    }
    u64 acc2[2] = {};
    const float* inb = g_g2 + (size_t)n * 64 * 65536;

    auto fill = [&](int ic0, int buf) {
        float* dI = sInD + buf * 9504;
        for (int i = tid; i < 9504; i += 256) {
            int j = i / 1188, rem = i - j * 1188, yy = rem / 66, xx = rem - yy * 66;
            int iy = y0 - 1 + yy, ix = x0 - 1 + xx;
            bool pr = (iy >= 0 && iy < 256 && ix >= 0 && ix < 256);
            const float* sp = pr ? &inb[(size_t)(ic0 + j) * 65536 + (size_t)iy * 256 + ix] : inb;
            cp4(saddr(dI + i), sp, pr);
        }
    };

    fill(0, 0);
    cp_commit();
    for (int c = 0; c < 8; c++) {
        int buf = c & 1;
        if (c + 1 < 8) fill((c + 1) * 8, (c + 1) & 1);
        cp_commit();
        cp_wait1();
        __syncthreads();
        const float* pI = sInD + buf * 9504;
        int ic0 = c * 8;
#pragma unroll
        for (int j = 0; j < 8; j++) {
            u64 wr2[9];
#pragma unroll
            for (int t = 0; t < 9; t++) { float t0 = sW[(ic0 + j) * 9 + t]; wr2[t] = pk(t0, t0); }
#pragma unroll
            for (int a = 0; a < 3; a++) {
                const float* rp = &pI[(j * 18 + ty + a) * 66 + tx * 4];
                float v[6];
#pragma unroll
                for (int cc = 0; cc < 6; cc++) v[cc] = rp[cc];
                u64 pv[5];
#pragma unroll
                for (int cc = 0; cc < 5; cc++) pv[cc] = pk(v[cc], v[cc + 1]);
#pragma unroll
                for (int bb = 0; bb < 3; bb++) {
                    fma2(acc2[0], pv[bb], wr2[a * 3 + bb]);
                    fma2(acc2[1], pv[bb + 2], wr2[a * 3 + bb]);
                }
            }
        }
        __syncthreads();
    }
    float bias = b[0];
    int oy = y0 + ty, ox = x0 + tx * 4;
    float* ob = out + (size_t)n * 65536 + (size_t)oy * 256 + ox;
    float2 f0 = unpk(acc2[0]), f1 = unpk(acc2[1]);
    ob[0] = f0.x + bias; ob[1] = f0.y + bias;
    ob[2] = f1.x + bias; ob[3] = f1.y + bias;
}

extern "C" void kernel_launch(void* const* d_in, const int* in_sizes, int n_in,
                              void* d_out, int out_size) {
    const float* x   = (const float*)d_in[0];
    const float* ew1 = (const float*)d_in[1];
    const float* eb1 = (const float*)d_in[2];
    const float* ew2 = (const float*)d_in[3];
    const float* eb2 = (const float*)d_in[4];
    const float* ew3 = (const float*)d_in[5];
    const float* eb3 = (const float*)d_in[6];
    const float* emb = (const float*)d_in[7];
    const float* dw1 = (const float*)d_in[8];
    const float* db1 = (const float*)d_in[9];
    const float* dw2 = (const float*)d_in[10];
    const float* db2 = (const float*)d_in[11];
    const float* dw3 = (const float*)d_in[12];
    const float* db3 = (const float*)d_in[13];
    float* out = (float*)d_out;

    float *pq, *pg1, *pg2;
    cudaGetSymbolAddress((void**)&pq,  g_q);
    cudaGetSymbolAddress((void**)&pg1, g_g1);
    cudaGetSymbolAddress((void**)&pg2, g_g2);

    const int smem2 = (2 * 2640 + 2 * 4096) * 4;   // 53888
    const int smem3 = (2 * 1632 + 2 * 4608) * 4;   // 49920
    const int smemT3 = (2 * 9504 + 576) * 4;       // 78336
    cudaFuncSetAttribute(k_conv2, cudaFuncAttributeMaxDynamicSharedMemorySize, smem2);
    cudaFuncSetAttribute(k_conv3, cudaFuncAttributeMaxDynamicSharedMemorySize, smem3);
    cudaFuncSetAttribute(k_convT3, cudaFuncAttributeMaxDynamicSharedMemorySize, smemT3);

    k_init<<<1, 512>>>();
    k_conv1<<<dim3(128, 32), 128>>>(x, ew1, eb1);
    k_conv2<<<dim3(2, 16, 32), 256, smem2>>>(ew2, eb2);
    k_conv3<<<dim3(2, 16, 32), 256, smem3>>>(ew3, eb3);
    k_ee<<<1, 512>>>(emb);
    k_vq<<<512, 256>>>(emb);
    k_gather<<<1024, 256>>>(emb);
    k_convT<<<dim3(2, 8, 32 * 16), 256>>>(pq, dw1, db1, pg1, 64, 128, 64, 128);
    k_convT<<<dim3(4, 16, 32 * 8), 256>>>(pg1, dw2, db2, pg2, 128, 64, 128, 256);
    k_convT3<<<dim3(4, 16, 32), 256, smemT3>>>(dw3, db3, out + 1);
    k_finalize<<<1, 512>>>(out, out_size);
}

// round 8
// speedup vs baseline: 1.2956x; 1.2956x over previous
#include <cuda_runtime.h>
#include <cuda_bf16.h>
#include <math.h>
#include <stdint.h>

typedef unsigned long long u64;

__device__ __forceinline__ u64 pk(float a, float b) {
    u64 r; asm("mov.b64 %0,{%1,%2};" : "=l"(r) : "f"(a), "f"(b)); return r;
}
__device__ __forceinline__ void fma2(u64& d, u64 a, u64 b) {
    asm("fma.rn.f32x2 %0, %1, %2, %0;" : "+l"(d) : "l"(a), "l"(b));
}
__device__ __forceinline__ float2 unpk(u64 x) {
    float2 f; asm("mov.b64 {%0,%1},%2;" : "=f"(f.x), "=f"(f.y) : "l"(x)); return f;
}
__device__ __forceinline__ uint32_t saddr(const void* p) {
    uint32_t a;
    asm("{.reg .u64 t; cvta.to.shared.u64 t,%1; cvt.u32.u64 %0,t;}" : "=r"(a) : "l"(p));
    return a;
}
__device__ __forceinline__ void cp4(uint32_t dst, const void* src, bool pred) {
    asm volatile("cp.async.ca.shared.global [%0], [%1], 4, %2;"
                 :: "r"(dst), "l"(src), "r"(pred ? 4u : 0u));
}
__device__ __forceinline__ void cp16(uint32_t dst, const void* src) {
    asm volatile("cp.async.cg.shared.global [%0], [%1], 16;" :: "r"(dst), "l"(src));
}
__device__ __forceinline__ void cp_commit() { asm volatile("cp.async.commit_group;"); }
__device__ __forceinline__ void cp_wait1()  { asm volatile("cp.async.wait_group 1;"); }
__device__ __forceinline__ void cp_wait0()  { asm volatile("cp.async.wait_group 0;"); }
__device__ __forceinline__ void ldsm4(uint32_t* r, uint32_t a) {
    asm volatile("ldmatrix.sync.aligned.m8n8.x4.shared.b16 {%0,%1,%2,%3}, [%4];"
        : "=r"(r[0]), "=r"(r[1]), "=r"(r[2]), "=r"(r[3]) : "r"(a));
}
__device__ __forceinline__ void mma16816(float* c, const uint32_t* a, uint32_t b0, uint32_t b1) {
    asm volatile("mma.sync.aligned.m16n8k16.row.col.f32.bf16.bf16.f32 "
        "{%0,%1,%2,%3},{%4,%5,%6,%7},{%8,%9},{%0,%1,%2,%3};"
        : "+f"(c[0]), "+f"(c[1]), "+f"(c[2]), "+f"(c[3])
        : "r"(a[0]), "r"(a[1]), "r"(a[2]), "r"(a[3]), "r"(b0), "r"(b1));
}

__device__ float g_h1[67108864];   // [32,128,128,128]
__device__ float g_h2[8388608];    // [32,64,64,64]
__device__ float g_z [8388608];    // NHWC
__device__ float g_q [8388608];    // NCHW
__device__ float g_g1[67108864];
__device__ float g_g2[134217728];
__device__ __align__(16) unsigned short g_wb1[262144];
__device__ __align__(16) unsigned short g_wb2[262144];
__device__ int    g_idx[131072];
__device__ float  g_ee[512];
__device__ float  g_counts[512];
__device__ double g_loss_sum;

__global__ void k_init() {
    int t = threadIdx.x;
    if (t < 512) g_counts[t] = 0.f;
    if (t == 0) g_loss_sum = 0.0;
}

__global__ void __launch_bounds__(128) k_conv1(const float* __restrict__ x,
                                               const float* __restrict__ w,
                                               const float* __restrict__ b) {
    __shared__ float sW[2048];
    __shared__ float sB[128];
    int ox = threadIdx.x, oy = blockIdx.x, n = blockIdx.y;
    for (int i = threadIdx.x; i < 2048; i += 128) sW[i] = w[i];
    sB[threadIdx.x] = b[threadIdx.x];
    __syncthreads();
    float p[16];
    const float* xb = x + (size_t)n * 65536;
#pragma unroll
    for (int ky = 0; ky < 4; ky++) {
        int iy = oy * 2 - 1 + ky;
#pragma unroll
        for (int kx = 0; kx < 4; kx++) {
            int ix = ox * 2 - 1 + kx;
            p[ky*4+kx] = (iy >= 0 && iy < 256 && ix >= 0 && ix < 256) ? xb[iy*256+ix] : 0.f;
        }
    }
    u64 p2[8];
#pragma unroll
    for (int u = 0; u < 8; u++) p2[u] = pk(p[2*u], p[2*u+1]);
    float* ob = g_h1 + (size_t)n * 2097152 + (size_t)oy * 128 + ox;
    for (int c = 0; c < 128; c++) {
        const ulonglong2* wp = (const ulonglong2*)&sW[c*16];
        u64 a2 = 0ull, b2 = 0ull;
#pragma unroll
        for (int u = 0; u < 4; u++) { ulonglong2 t = wp[u]; fma2(a2, p2[2*u], t.x); fma2(b2, p2[2*u+1], t.y); }
        float2 fa = unpk(a2), fb = unpk(b2);
        ob[(size_t)c * 16384] = fmaxf((fa.x+fa.y)+(fb.x+fb.y)+sB[c], 0.f);
    }
}

__global__ void __launch_bounds__(256) k_conv2(const float* __restrict__ w,
                                               const float* __restrict__ b) {
    extern __shared__ float sm2[];
    float* sInD = sm2;
    float* sWD  = sm2 + 2*4752;
    int tid = threadIdx.x, tx = tid & 7, ty = (tid >> 3) & 7, tz = tid >> 6;
    int n = blockIdx.z, oy0 = blockIdx.y*8, ox0 = blockIdx.x*32;
    const float* inb = g_h1 + (size_t)n * 2097152;
    u64 acc2[4][8] = {};
    const int IY0 = oy0*2-1, IX0 = ox0*2-1;
    auto fill = [&](int ic0, int buf) {
        float* dI = sInD + buf*4752;
        for (int i = tid; i < 4752; i += 256) {
            int j = i/1188, rem = i - j*1188, yy = rem/66, xx = rem - yy*66;
            int iy = IY0+yy, ix = IX0+xx;
            bool pr = (iy >= 0 && iy < 128 && ix >= 0 && ix < 128);
            cp4(saddr(dI+i), pr ? &inb[((size_t)(ic0+j)*128+iy)*128+ix] : inb, pr);
        }
        float* dW = sWD + buf*4096;
        for (int i = tid; i < 4096; i += 256) {
            int j = i>>10, rem = i & 1023, t = rem>>6, oc = rem & 63;
            cp4(saddr(dW+i), &w[((size_t)(oc<<7)+ic0+j)*16+t], true);
        }
    };
    fill(0, 0); cp_commit();
    for (int c = 0; c < 32; c++) {
        int buf = c & 1;
        if (c+1 < 32) fill((c+1)*4, (c+1)&1);
        cp_commit(); cp_wait1(); __syncthreads();
        const float* pI = sInD + buf*4752;
        const float* pW = sWD + buf*4096;
#pragma unroll
        for (int j = 0; j < 4; j++)
#pragma unroll
        for (int ky = 0; ky < 4; ky++) {
            const float* rp = &pI[(j*18+ty*2+ky)*66+tx*8];
            float v[10];
#pragma unroll
            for (int cc = 0; cc < 10; cc++) v[cc] = rp[cc];
#pragma unroll
            for (int kx = 0; kx < 4; kx++) {
                u64 v0 = pk(v[kx],v[kx]), v1 = pk(v[kx+2],v[kx+2]);
                u64 v2 = pk(v[kx+4],v[kx+4]), v3 = pk(v[kx+6],v[kx+6]);
                const ulonglong2* wp = (const ulonglong2*)&pW[((j<<4)+(ky<<2)+kx)*64+tz*16];
                u64 wv[8];
#pragma unroll
                for (int u = 0; u < 4; u++) { ulonglong2 t = wp[u]; wv[2*u]=t.x; wv[2*u+1]=t.y; }
#pragma unroll
                for (int o = 0; o < 8; o++) {
                    fma2(acc2[0][o], v0, wv[o]); fma2(acc2[1][o], v1, wv[o]);
                    fma2(acc2[2][o], v2, wv[o]); fma2(acc2[3][o], v3, wv[o]);
                }
            }
        }
        __syncthreads();
    }
    int oy = oy0 + ty;
#pragma unroll
    for (int o = 0; o < 8; o++) {
        int oce = tz*16 + 2*o;
        float be = b[oce], bo = b[oce+1];
        float2 a0 = unpk(acc2[0][o]), a1 = unpk(acc2[1][o]), a2 = unpk(acc2[2][o]), a3 = unpk(acc2[3][o]);
        float4 re, ro;
        re.x = fmaxf(a0.x+be,0.f); re.y = fmaxf(a1.x+be,0.f); re.z = fmaxf(a2.x+be,0.f); re.w = fmaxf(a3.x+be,0.f);
        ro.x = fmaxf(a0.y+bo,0.f); ro.y = fmaxf(a1.y+bo,0.f); ro.z = fmaxf(a2.y+bo,0.f); ro.w = fmaxf(a3.y+bo,0.f);
        *(float4*)&g_h2[(((size_t)n*64+oce)*64+oy)*64+ox0+tx*4] = re;
        *(float4*)&g_h2[(((size_t)n*64+oce+1)*64+oy)*64+ox0+tx*4] = ro;
    }
}

__global__ void __launch_bounds__(256) k_conv3(const float* __restrict__ w,
                                               const float* __restrict__ b) {
    extern __shared__ float sm3[];
    float* sInD = sm3;
    float* sWD  = sm3 + 2*2720;
    int tid = threadIdx.x, tx = tid & 7, ty = (tid >> 3) & 7, tz = tid >> 6;
    int n = blockIdx.z, oy0 = blockIdx.y*8, ox0 = blockIdx.x*32;
    const float* inb = g_h2 + (size_t)n * 262144;
    u64 acc2[4][8] = {};
    auto fill = [&](int ic0, int buf) {
        float* dI = sInD + buf*2720;
        for (int i = tid; i < 2720; i += 256) {
            int j = i/340, rem = i - j*340, yy = rem/34, xx = rem - yy*34;
            int iy = oy0-1+yy, ix = ox0-1+xx;
            bool pr = (iy >= 0 && iy < 64 && ix >= 0 && ix < 64);
            cp4(saddr(dI+i), pr ? &inb[((size_t)(ic0+j)*64+iy)*64+ix] : inb, pr);
        }
        float* dW = sWD + buf*4608;
        for (int i = tid; i < 4608; i += 256) {
            int j = i/576, rem = i - j*576, t = rem>>6, oc = rem & 63;
            cp4(saddr(dW+i), &w[((size_t)oc*64+ic0+j)*9+t], true);
        }
    };
    fill(0, 0); cp_commit();
    for (int c = 0; c < 8; c++) {
        int buf = c & 1;
        if (c+1 < 8) fill((c+1)*8, (c+1)&1);
        cp_commit(); cp_wait1(); __syncthreads();
        const float* pI = sInD + buf*2720;
        const float* pW = sWD + buf*4608;
#pragma unroll
        for (int j = 0; j < 8; j++)
#pragma unroll
        for (int ky = 0; ky < 3; ky++) {
            const float* rp = &pI[(j*10+ty+ky)*34+tx*4];
            u64 vv[6];
#pragma unroll
            for (int cc = 0; cc < 6; cc++) { float t = rp[cc]; vv[cc] = pk(t,t); }
#pragma unroll
            for (int kx = 0; kx < 3; kx++) {
                const ulonglong2* wp = (const ulonglong2*)&pW[(j*9+ky*3+kx)*64+tz*16];
                u64 wv[8];
#pragma unroll
                for (int u = 0; u < 4; u++) { ulonglong2 t = wp[u]; wv[2*u]=t.x; wv[2*u+1]=t.y; }
#pragma unroll
                for (int q = 0; q < 4; q++)
#pragma unroll
                for (int o = 0; o < 8; o++) fma2(acc2[q][o], vv[q+kx], wv[o]);
            }
        }
        __syncthreads();
    }
    int oy = oy0 + ty;
    float bb[16];
#pragma unroll
    for (int i = 0; i < 16; i++) bb[i] = b[tz*16+i];
#pragma unroll
    for (int q = 0; q < 4; q++) {
        float* zp = g_z + (((size_t)n*64+oy)*64 + ox0+tx*4+q)*64 + tz*16;
#pragma unroll
        for (int o = 0; o < 8; o++) {
            float2 e = unpk(acc2[q][o]);
            float2 r; r.x = e.x + bb[2*o]; r.y = e.y + bb[2*o+1];
            ((float2*)zp)[o] = r;
        }
    }
}

__global__ void k_ee(const float* __restrict__ emb) {
    int k = threadIdx.x;
    float s = 0.f;
    for (int d = 0; d < 64; d++) { float e = emb[d*512+k]; s += e*e; }
    g_ee[k] = s;
}

__global__ void __launch_bounds__(256) k_vq(const float* __restrict__ emb) {
    __shared__ float sE[64*68];
    __shared__ float sEE[64];
    int tid = threadIdx.x;
    int row = blockIdx.x*256 + tid;
    u64 zr2[32];
    const float4* zp = (const float4*)(g_z + (size_t)row*64);
#pragma unroll
    for (int j = 0; j < 16; j++) { float4 t = zp[j]; zr2[2*j] = pk(t.x,t.y); zr2[2*j+1] = pk(t.z,t.w); }
    float best = 3.4e38f;
    int bi = 0;
    for (int kc = 0; kc < 512; kc += 64) {
        __syncthreads();
        for (int i = tid; i < 4096; i += 256) { int d = i>>6, k = i&63; sE[k*68+d] = emb[d*512+kc+k]; }
        if (tid < 64) sEE[tid] = g_ee[kc+tid];
        __syncthreads();
        for (int k = 0; k < 64; k++) {
            const ulonglong2* ep = (const ulonglong2*)&sE[k*68];
            u64 sa = 0ull, sb = 0ull;
#pragma unroll
            for (int jj = 0; jj < 16; jj++) { ulonglong2 e = ep[jj]; fma2(sa, zr2[2*jj], e.x); fma2(sb, zr2[2*jj+1], e.y); }
            float2 fa = unpk(sa), fb = unpk(sb);
            float dd = sEE[k] - 2.f*((fa.x+fa.y)+(fb.x+fb.y));
            if (dd < best) { best = dd; bi = kc + k; }
        }
    }
    g_idx[row] = bi;
    atomicAdd(&g_counts[bi], 1.f);
}

__global__ void __launch_bounds__(256) k_gather(const float* __restrict__ emb) {
    __shared__ float sQ[8192];
    __shared__ float sRed[256];
    int tid = threadIdx.x;
    int r0 = blockIdx.x*128;
    int rl = tid & 127, half = tid >> 7;
    int r = r0 + rl;
    int id = g_idx[r];
    const float4* z4 = (const float4*)(g_z + (size_t)r*64 + half*32);
    float ls = 0.f;
#pragma unroll
    for (int jj = 0; jj < 8; jj++) {
        float4 zv = z4[jj];
        int d = half*32 + jj*4;
        float e0 = emb[(d+0)*512+id], e1 = emb[(d+1)*512+id], e2 = emb[(d+2)*512+id], e3 = emb[(d+3)*512+id];
        float d0 = e0-zv.x, d1 = e1-zv.y, d2 = e2-zv.z, d3 = e3-zv.w;
        ls += d0*d0 + d1*d1 + d2*d2 + d3*d3;
        sQ[(d+0)*128+rl] = e0; sQ[(d+1)*128+rl] = e1; sQ[(d+2)*128+rl] = e2; sQ[(d+3)*128+rl] = e3;
    }
    __syncthreads();
    int n = r0 >> 12;
    float* qb = g_q + ((size_t)n << 18) + (r0 & 4095);
    for (int i = tid; i < 8192; i += 256) qb[(size_t)(i>>7)*4096 + (i&127)] = sQ[i];
    sRed[tid] = ls;
    __syncthreads();
    for (int s = 128; s > 0; s >>= 1) { if (tid < s) sRed[tid] += sRed[tid+s]; __syncthreads(); }
    if (tid == 0) atomicAdd(&g_loss_sum, (double)sRed[0]);
}

__global__ void k_finalize(float* __restrict__ out, int out_size) {
    __shared__ float red[512];
    int t = threadIdx.x;
    float p = g_counts[t] * (1.f/131072.f);
    red[t] = p * logf(p + 1e-10f);
    __syncthreads();
    for (int s = 256; s > 0; s >>= 1) { if (t < s) red[t] += red[t+s]; __syncthreads(); }
    if (t == 0) { out[out_size-1] = expf(-red[0]); out[0] = (float)(g_loss_sum * (1.25/8388608.0)); }
}

// repack convT weights: dst[h][c][part][n=dy*64+ocl][k swizzled 64] bf16 hi/lo
__global__ void k_repack(const float* __restrict__ w, unsigned short* __restrict__ dst,
                         int C, int ICC, int OCt) {
    int idx = blockIdx.x*256 + threadIdx.x;
    int k = idx & 63, n = (idx >> 6) & 127, part = (idx >> 13) & 1, rest = idx >> 14;
    int c = rest % C, h = rest / C;
    int dy = n >> 6, ocl = n & 63, dx = h & 1, och = h >> 1;
    int tap = c / ICC, icc = c - tap*ICC;
    int ty = tap >> 1, txx = tap & 1;
    int ky = dy - 2*ty + 1, kx = dx - 2*txx + 1;
    int ic = icc*64 + k, oc = och*64 + ocl;
    float v = (ky >= 0 && kx >= 0) ? w[((size_t)ic*OCt + oc)*9 + ky*3 + kx] : 0.f;
    __nv_bfloat16 hh = __float2bfloat16(v);
    unsigned short bits = (part == 0) ? __bfloat16_as_ushort(hh)
        : __bfloat16_as_ushort(__float2bfloat16(v - __bfloat162float(hh)));
    dst[(size_t)((h*C + c)*2 + part)*8192 + n*64 + ((((unsigned)k>>3) ^ (n&7))<<3) + (k&7)] = bits;
}

// mma.sync transposed conv: per CTA M=128 sites x N=128(dy*64+ocl) x K=64/chunk, 3-pass bf16
template<int INS, int IC, int OC>
__global__ void __launch_bounds__(256) k_convT_mma(const float* __restrict__ in,
    const unsigned short* __restrict__ wb, const float* __restrict__ bias, float* __restrict__ out) {
    constexpr int ICC = IC/64, C = 4*ICC, XW = INS, ROWS = 128/XW, OUTS = 2*INS;
    constexpr int LOGXW = (INS == 64) ? 6 : 7;
    extern __shared__ char smg[];
    uint32_t sb = saddr(smg);
    float* sBias = (float*)(smg + 65536);
    int tid = threadIdx.x, lane = tid & 31, wid = tid >> 5;
    int y0 = blockIdx.x*ROWS, nb = blockIdx.y, h = blockIdx.z;
    int dx = h & 1, och = h >> 1;
    int m0w = (wid >> 1) * 32, n0w = (wid & 1) * 64;
    const float* inb = in + (size_t)nb*IC*INS*INS;
    if (tid < 64) sBias[tid] = bias[och*64 + tid];
    float acc[2][8][4];
#pragma unroll
    for (int i = 0; i < 2; i++)
#pragma unroll
    for (int j = 0; j < 8; j++)
#pragma unroll
    for (int q = 0; q < 4; q++) acc[i][j][q] = 0.f;

    for (int c = 0; c < C; c++) {
        __syncthreads();
        // A fill: bf16 hi/lo, swizzled [m][k]
        {
            int tap = c / ICC, icc = c - tap*ICC;
            int tty = tap >> 1, ttx = tap & 1;
            int kbase = wid * 8;
#pragma unroll
            for (int kk2 = 0; kk2 < 4; kk2++) {
                int k = kbase + kk2*2;
                const float* s0 = inb + (size_t)(icc*64 + k)*INS*INS;
                const float* s1 = s0 + (size_t)INS*INS;
#pragma unroll
                for (int mb = 0; mb < 4; mb++) {
                    int m = mb*32 + lane;
                    int rr = m >> LOGXW, x = m & (XW-1);
                    int y = y0 + rr + tty, xx = x + ttx;
                    bool ok = (y < INS) && (xx < INS);
                    size_t off = (size_t)y*INS + xx;
                    float v0 = ok ? s0[off] : 0.f;
                    float v1 = ok ? s1[off] : 0.f;
                    float h0 = __bfloat162float(__float2bfloat16(v0));
                    float h1 = __bfloat162float(__float2bfloat16(v1));
                    uint32_t wofs = (uint32_t)m*128 + ((((unsigned)k>>3) ^ (m&7))<<4) + (k&7)*2;
                    uint32_t hw, lw;
                    asm("cvt.rn.bf16x2.f32 %0, %1, %2;" : "=r"(hw) : "f"(v1), "f"(v0));
                    asm("cvt.rn.bf16x2.f32 %0, %1, %2;" : "=r"(lw) : "f"(v1-h1), "f"(v0-h0));
                    asm volatile("st.shared.b32 [%0], %1;" :: "r"(sb + wofs), "r"(hw));
                    asm volatile("st.shared.b32 [%0], %1;" :: "r"(sb + 16384 + wofs), "r"(lw));
                }
            }
        }
        // B fill: pre-swizzled hi/lo, linear cp.async
        for (int i = tid; i < 2048; i += 256) {
            int part = i >> 10, wi = i & 1023;
            cp16(sb + 32768 + part*16384 + wi*16,
                 wb + (size_t)((h*C + c)*2 + part)*8192 + wi*8);
        }
        cp_commit(); cp_wait0();
        __syncthreads();
        // compute: 3 passes x 4 k-steps
#pragma unroll
        for (int pass = 0; pass < 3; pass++) {
            uint32_t Ab = sb + ((pass == 2) ? 16384 : 0);
            uint32_t Bb = sb + 32768 + ((pass == 1) ? 16384 : 0);
#pragma unroll
            for (int ks = 0; ks < 4; ks++) {
                int lrow = lane & 15, lcol = lane >> 4;
                uint32_t a[2][4], bq[4][4];
#pragma unroll
                for (int mi = 0; mi < 2; mi++) {
                    int rw = m0w + mi*16 + lrow;
                    ldsm4(a[mi], Ab + (uint32_t)rw*128 + ((((unsigned)(ks*2+lcol)) ^ (rw&7))<<4));
                }
#pragma unroll
                for (int nq = 0; nq < 4; nq++) {
                    int rw = n0w + nq*16 + lrow;
                    ldsm4(bq[nq], Bb + (uint32_t)rw*128 + ((((unsigned)(ks*2+lcol)) ^ (rw&7))<<4));
                }
#pragma unroll
                for (int mi = 0; mi < 2; mi++)
#pragma unroll
                for (int nj = 0; nj < 8; nj++)
                    mma16816(acc[mi][nj], a[mi], bq[nj>>1][nj&1], bq[nj>>1][(nj&1)+2]);
            }
        }
    }
    // epilogue
    int grow = lane >> 2, gcol = (lane & 3)*2;
#pragma unroll
    for (int mi = 0; mi < 2; mi++)
#pragma unroll
    for (int rg2 = 0; rg2 < 2; rg2++) {
        int m = m0w + mi*16 + grow + rg2*8;
        int rr = m >> LOGXW, x = m & (XW-1);
        int ox = 2*x + dx;
        int oyb = 2*(y0 + rr);
#pragma unroll
        for (int nj = 0; nj < 8; nj++)
#pragma unroll
        for (int cc = 0; cc < 2; cc++) {
            int n = n0w + nj*8 + gcol + cc;
            int dy = n >> 6, ocl = n & 63;
            float v = fmaxf(acc[mi][nj][rg2*2 + cc] + sBias[ocl], 0.f);
            out[(((size_t)nb*OC + och*64 + ocl)*OUTS + oyb + dy)*OUTS + ox] = v;
        }
    }
}

__global__ void __launch_bounds__(256) k_convT3(const float* __restrict__ w,
                                                const float* __restrict__ b,
                                                float* __restrict__ out) {
    extern __shared__ float smT[];
    float* sInD = smT;
    float* sW   = smT + 2*9504;
    int tid = threadIdx.x, tx = tid & 15, ty = tid >> 4;
    int n = blockIdx.z, y0 = blockIdx.y*16, x0 = blockIdx.x*64;
    for (int i = tid; i < 576; i += 256) { int ic = i/9, t = i - ic*9; sW[i] = w[ic*9 + (8-t)]; }
    u64 acc2[2] = {};
    const float* inb = g_g2 + (size_t)n * 64 * 65536;
    auto fill = [&](int ic0, int buf) {
        float* dI = sInD + buf*9504;
        for (int i = tid; i < 9504; i += 256) {
            int j = i/1188, rem = i - j*1188, yy = rem/66, xx = rem - yy*66;
            int iy = y0-1+yy, ix = x0-1+xx;
            bool pr = (iy >= 0 && iy < 256 && ix >= 0 && ix < 256);
            cp4(saddr(dI+i), pr ? &inb[(size_t)(ic0+j)*65536 + (size_t)iy*256 + ix] : inb, pr);
        }
    };
    fill(0, 0); cp_commit();
    for (int c = 0; c < 8; c++) {
        int buf = c & 1;
        if (c+1 < 8) fill((c+1)*8, (c+1)&1);
        cp_commit(); cp_wait1(); __syncthreads();
        const float* pI = sInD + buf*9504;
        int ic0 = c*8;
#pragma unroll
        for (int j = 0; j < 8; j++) {
            u64 wr2[9];
#pragma unroll
            for (int t = 0; t < 9; t++) { float t0 = sW[(ic0+j)*9+t]; wr2[t] = pk(t0,t0); }
#pragma unroll
            for (int a = 0; a < 3; a++) {
                const float* rp = &pI[(j*18+ty+a)*66+tx*4];
                float v[6];
#pragma unroll
                for (int cc = 0; cc < 6; cc++) v[cc] = rp[cc];
                u64 pv[5];
#pragma unroll
                for (int cc = 0; cc < 5; cc++) pv[cc] = pk(v[cc], v[cc+1]);
#pragma unroll
                for (int bb = 0; bb < 3; bb++) { fma2(acc2[0], pv[bb], wr2[a*3+bb]); fma2(acc2[1], pv[bb+2], wr2[a*3+bb]); }
            }
        }
        __syncthreads();
    }
    float bias = b[0];
    float* ob = out + (size_t)n*65536 + (size_t)(y0+ty)*256 + x0 + tx*4;
    float2 f0 = unpk(acc2[0]), f1 = unpk(acc2[1]);
    ob[0] = f0.x + bias; ob[1] = f0.y + bias; ob[2] = f1.x + bias; ob[3] = f1.y + bias;
}

extern "C" void kernel_launch(void* const* d_in, const int* in_sizes, int n_in,
                              void* d_out, int out_size) {
    const float* x   = (const float*)d_in[0];
    const float* ew1 = (const float*)d_in[1];
    const float* eb1 = (const float*)d_in[2];
    const float* ew2 = (const float*)d_in[3];
    const float* eb2 = (const float*)d_in[4];
    const float* ew3 = (const float*)d_in[5];
    const float* eb3 = (const float*)d_in[6];
    const float* emb = (const float*)d_in[7];
    const float* dw1 = (const float*)d_in[8];
    const float* db1 = (const float*)d_in[9];
    const float* dw2 = (const float*)d_in[10];
    const float* db2 = (const float*)d_in[11];
    const float* dw3 = (const float*)d_in[12];
    const float* db3 = (const float*)d_in[13];
    float* out = (float*)d_out;

    float *pq, *pg1, *pg2;
    unsigned short *pw1, *pw2;
    cudaGetSymbolAddress((void**)&pq,  g_q);
    cudaGetSymbolAddress((void**)&pg1, g_g1);
    cudaGetSymbolAddress((void**)&pg2, g_g2);
    cudaGetSymbolAddress((void**)&pw1, g_wb1);
    cudaGetSymbolAddress((void**)&pw2, g_wb2);

    const int smem2 = (2*4752 + 2*4096)*4;
    const int smem3 = (2*2720 + 2*4608)*4;
    const int smemT3 = (2*9504 + 576)*4;
    const int smemM = 65536 + 256;
    cudaFuncSetAttribute(k_conv2, cudaFuncAttributeMaxDynamicSharedMemorySize, smem2);
    cudaFuncSetAttribute(k_conv3, cudaFuncAttributeMaxDynamicSharedMemorySize, smem3);
    cudaFuncSetAttribute(k_convT3, cudaFuncAttributeMaxDynamicSharedMemorySize, smemT3);
    cudaFuncSetAttribute(k_convT_mma<64,64,128>,  cudaFuncAttributeMaxDynamicSharedMemorySize, smemM);
    cudaFuncSetAttribute(k_convT_mma<128,128,64>, cudaFuncAttributeMaxDynamicSharedMemorySize, smemM);

    k_init<<<1, 512>>>();
    k_repack<<<1024, 256>>>(dw1, pw1, 4, 1, 128);
    k_repack<<<1024, 256>>>(dw2, pw2, 8, 2, 64);
    k_conv1<<<dim3(128, 32), 128>>>(x, ew1, eb1);
    k_conv2<<<dim3(2, 8, 32), 256, smem2>>>(ew2, eb2);
    k_conv3<<<dim3(2, 8, 32), 256, smem3>>>(ew3, eb3);
    k_ee<<<1, 512>>>(emb);
    k_vq<<<512, 256>>>(emb);
    k_gather<<<1024, 256>>>(emb);
    k_convT_mma<64,64,128><<<dim3(32, 32, 4), 256, smemM>>>(pq, pw1, db1, pg1);
    k_convT_mma<128,128,64><<<dim3(128, 32, 2), 256, smemM>>>(pg1, pw2, db2, pg2);
    k_convT3<<<dim3(4, 16, 32), 256, smemT3>>>(dw3, db3, out + 1);
    k_finalize<<<1, 512>>>(out, out_size);
}

// round 9
// speedup vs baseline: 1.4959x; 1.1546x over previous
#include <cuda_runtime.h>
#include <cuda_bf16.h>
#include <math.h>
#include <stdint.h>

typedef unsigned long long u64;

__device__ __forceinline__ u64 pk(float a, float b) {
    u64 r; asm("mov.b64 %0,{%1,%2};" : "=l"(r) : "f"(a), "f"(b)); return r;
}
__device__ __forceinline__ void fma2(u64& d, u64 a, u64 b) {
    asm("fma.rn.f32x2 %0, %1, %2, %0;" : "+l"(d) : "l"(a), "l"(b));
}
__device__ __forceinline__ float2 unpk(u64 x) {
    float2 f; asm("mov.b64 {%0,%1},%2;" : "=f"(f.x), "=f"(f.y) : "l"(x)); return f;
}
__device__ __forceinline__ uint32_t saddr(const void* p) {
    uint32_t a;
    asm("{.reg .u64 t; cvta.to.shared.u64 t,%1; cvt.u32.u64 %0,t;}" : "=r"(a) : "l"(p));
    return a;
}
__device__ __forceinline__ void cp4(uint32_t dst, const void* src, bool pred) {
    asm volatile("cp.async.ca.shared.global [%0], [%1], 4, %2;"
                 :: "r"(dst), "l"(src), "r"(pred ? 4u : 0u));
}
__device__ __forceinline__ void cp16(uint32_t dst, const void* src) {
    asm volatile("cp.async.cg.shared.global [%0], [%1], 16;" :: "r"(dst), "l"(src));
}
__device__ __forceinline__ void cp_commit() { asm volatile("cp.async.commit_group;"); }
__device__ __forceinline__ void cp_wait1()  { asm volatile("cp.async.wait_group 1;"); }
__device__ __forceinline__ void cp_wait0()  { asm volatile("cp.async.wait_group 0;"); }
__device__ __forceinline__ void ldsm4(uint32_t* r, uint32_t a) {
    asm volatile("ldmatrix.sync.aligned.m8n8.x4.shared.b16 {%0,%1,%2,%3}, [%4];"
        : "=r"(r[0]), "=r"(r[1]), "=r"(r[2]), "=r"(r[3]) : "r"(a));
}
__device__ __forceinline__ void mma16816(float* c, const uint32_t* a, uint32_t b0, uint32_t b1) {
    asm volatile("mma.sync.aligned.m16n8k16.row.col.f32.bf16.bf16.f32 "
        "{%0,%1,%2,%3},{%4,%5,%6,%7},{%8,%9},{%0,%1,%2,%3};"
        : "+f"(c[0]), "+f"(c[1]), "+f"(c[2]), "+f"(c[3])
        : "r"(a[0]), "r"(a[1]), "r"(a[2]), "r"(a[3]), "r"(b0), "r"(b1));
}
__device__ __forceinline__ void st32(uint32_t a, uint32_t v) {
    asm volatile("st.shared.b32 [%0], %1;" :: "r"(a), "r"(v));
}

__device__ float g_h1[67108864];   // [32,128,128,128]
__device__ float g_h2[8388608];    // [32,64,64,64]
__device__ float g_z [8388608];    // NHWC
__device__ float g_q [8388608];    // NCHW
__device__ float g_g1[67108864];
__device__ float g_g2[134217728];
__device__ __align__(16) unsigned short g_wb1[262144];
__device__ __align__(16) unsigned short g_wb2[262144];
__device__ int    g_idx[131072];
__device__ float  g_ee[512];
__device__ float  g_counts[512];
__device__ double g_loss_sum;

__global__ void k_init() {
    int t = threadIdx.x;
    if (t < 512) g_counts[t] = 0.f;
    if (t == 0) g_loss_sum = 0.0;
}

__global__ void __launch_bounds__(128) k_conv1(const float* __restrict__ x,
                                               const float* __restrict__ w,
                                               const float* __restrict__ b) {
    __shared__ float sW[2048];
    __shared__ float sB[128];
    int ox = threadIdx.x, oy = blockIdx.x, n = blockIdx.y;
    for (int i = threadIdx.x; i < 2048; i += 128) sW[i] = w[i];
    sB[threadIdx.x] = b[threadIdx.x];
    __syncthreads();
    float p[16];
    const float* xb = x + (size_t)n * 65536;
#pragma unroll
    for (int ky = 0; ky < 4; ky++) {
        int iy = oy * 2 - 1 + ky;
#pragma unroll
        for (int kx = 0; kx < 4; kx++) {
            int ix = ox * 2 - 1 + kx;
            p[ky*4+kx] = (iy >= 0 && iy < 256 && ix >= 0 && ix < 256) ? xb[iy*256+ix] : 0.f;
        }
    }
    u64 p2[8];
#pragma unroll
    for (int u = 0; u < 8; u++) p2[u] = pk(p[2*u], p[2*u+1]);
    float* ob = g_h1 + (size_t)n * 2097152 + (size_t)oy * 128 + ox;
    for (int c = 0; c < 128; c++) {
        const ulonglong2* wp = (const ulonglong2*)&sW[c*16];
        u64 a2 = 0ull, b2 = 0ull;
#pragma unroll
        for (int u = 0; u < 4; u++) { ulonglong2 t = wp[u]; fma2(a2, p2[2*u], t.x); fma2(b2, p2[2*u+1], t.y); }
        float2 fa = unpk(a2), fb = unpk(b2);
        ob[(size_t)c * 16384] = fmaxf((fa.x+fa.y)+(fb.x+fb.y)+sB[c], 0.f);
    }
}

__global__ void __launch_bounds__(256) k_conv2(const float* __restrict__ w,
                                               const float* __restrict__ b) {
    extern __shared__ float sm2[];
    float* sInD = sm2;
    float* sWD  = sm2 + 2*4752;
    int tid = threadIdx.x, tx = tid & 7, ty = (tid >> 3) & 7, tz = tid >> 6;
    int n = blockIdx.z, oy0 = blockIdx.y*8, ox0 = blockIdx.x*32;
    const float* inb = g_h1 + (size_t)n * 2097152;
    u64 acc2[4][8] = {};
    const int IY0 = oy0*2-1, IX0 = ox0*2-1;
    auto fill = [&](int ic0, int buf) {
        float* dI = sInD + buf*4752;
        for (int i = tid; i < 4752; i += 256) {
            int j = i/1188, rem = i - j*1188, yy = rem/66, xx = rem - yy*66;
            int iy = IY0+yy, ix = IX0+xx;
            bool pr = (iy >= 0 && iy < 128 && ix >= 0 && ix < 128);
            cp4(saddr(dI+i), pr ? &inb[((size_t)(ic0+j)*128+iy)*128+ix] : inb, pr);
        }
        float* dW = sWD + buf*4096;
        for (int i = tid; i < 4096; i += 256) {
            int j = i>>10, rem = i & 1023, t = rem>>6, oc = rem & 63;
            cp4(saddr(dW+i), &w[((size_t)(oc<<7)+ic0+j)*16+t], true);
        }
    };
    fill(0, 0); cp_commit();
    for (int c = 0; c < 32; c++) {
        int buf = c & 1;
        if (c+1 < 32) fill((c+1)*4, (c+1)&1);
        cp_commit(); cp_wait1(); __syncthreads();
        const float* pI = sInD + buf*4752;
        const float* pW = sWD + buf*4096;
#pragma unroll
        for (int j = 0; j < 4; j++)
#pragma unroll
        for (int ky = 0; ky < 4; ky++) {
            const float* rp = &pI[(j*18+ty*2+ky)*66+tx*8];
            float v[10];
#pragma unroll
            for (int cc = 0; cc < 10; cc++) v[cc] = rp[cc];
#pragma unroll
            for (int kx = 0; kx < 4; kx++) {
                u64 v0 = pk(v[kx],v[kx]), v1 = pk(v[kx+2],v[kx+2]);
                u64 v2 = pk(v[kx+4],v[kx+4]), v3 = pk(v[kx+6],v[kx+6]);
                const ulonglong2* wp = (const ulonglong2*)&pW[((j<<4)+(ky<<2)+kx)*64+tz*16];
                u64 wv[8];
#pragma unroll
                for (int u = 0; u < 4; u++) { ulonglong2 t = wp[u]; wv[2*u]=t.x; wv[2*u+1]=t.y; }
#pragma unroll
                for (int o = 0; o < 8; o++) {
                    fma2(acc2[0][o], v0, wv[o]); fma2(acc2[1][o], v1, wv[o]);
                    fma2(acc2[2][o], v2, wv[o]); fma2(acc2[3][o], v3, wv[o]);
                }
            }
        }
        __syncthreads();
    }
    int oy = oy0 + ty;
#pragma unroll
    for (int o = 0; o < 8; o++) {
        int oce = tz*16 + 2*o;
        float be = b[oce], bo = b[oce+1];
        float2 a0 = unpk(acc2[0][o]), a1 = unpk(acc2[1][o]), a2 = unpk(acc2[2][o]), a3 = unpk(acc2[3][o]);
        float4 re, ro;
        re.x = fmaxf(a0.x+be,0.f); re.y = fmaxf(a1.x+be,0.f); re.z = fmaxf(a2.x+be,0.f); re.w = fmaxf(a3.x+be,0.f);
        ro.x = fmaxf(a0.y+bo,0.f); ro.y = fmaxf(a1.y+bo,0.f); ro.z = fmaxf(a2.y+bo,0.f); ro.w = fmaxf(a3.y+bo,0.f);
        *(float4*)&g_h2[(((size_t)n*64+oce)*64+oy)*64+ox0+tx*4] = re;
        *(float4*)&g_h2[(((size_t)n*64+oce+1)*64+oy)*64+ox0+tx*4] = ro;
    }
}

__global__ void __launch_bounds__(256) k_conv3(const float* __restrict__ w,
                                               const float* __restrict__ b) {
    extern __shared__ float sm3[];
    float* sInD = sm3;
    float* sWD  = sm3 + 2*2720;
    int tid = threadIdx.x, tx = tid & 7, ty = (tid >> 3) & 7, tz = tid >> 6;
    int n = blockIdx.z, oy0 = blockIdx.y*8, ox0 = blockIdx.x*32;
    const float* inb = g_h2 + (size_t)n * 262144;
    u64 acc2[4][8] = {};
    auto fill = [&](int ic0, int buf) {
        float* dI = sInD + buf*2720;
        for (int i = tid; i < 2720; i += 256) {
            int j = i/340, rem = i - j*340, yy = rem/34, xx = rem - yy*34;
            int iy = oy0-1+yy, ix = ox0-1+xx;
            bool pr = (iy >= 0 && iy < 64 && ix >= 0 && ix < 64);
            cp4(saddr(dI+i), pr ? &inb[((size_t)(ic0+j)*64+iy)*64+ix] : inb, pr);
        }
        float* dW = sWD + buf*4608;
        for (int i = tid; i < 4608; i += 256) {
            int j = i/576, rem = i - j*576, t = rem>>6, oc = rem & 63;
            cp4(saddr(dW+i), &w[((size_t)oc*64+ic0+j)*9+t], true);
        }
    };
    fill(0, 0); cp_commit();
    for (int c = 0; c < 8; c++) {
        int buf = c & 1;
        if (c+1 < 8) fill((c+1)*8, (c+1)&1);
        cp_commit(); cp_wait1(); __syncthreads();
        const float* pI = sInD + buf*2720;
        const float* pW = sWD + buf*4608;
#pragma unroll
        for (int j = 0; j < 8; j++)
#pragma unroll
        for (int ky = 0; ky < 3; ky++) {
            const float* rp = &pI[(j*10+ty+ky)*34+tx*4];
            u64 vv[6];
#pragma unroll
            for (int cc = 0; cc < 6; cc++) { float t = rp[cc]; vv[cc] = pk(t,t); }
#pragma unroll
            for (int kx = 0; kx < 3; kx++) {
                const ulonglong2* wp = (const ulonglong2*)&pW[(j*9+ky*3+kx)*64+tz*16];
                u64 wv[8];
#pragma unroll
                for (int u = 0; u < 4; u++) { ulonglong2 t = wp[u]; wv[2*u]=t.x; wv[2*u+1]=t.y; }
#pragma unroll
                for (int q = 0; q < 4; q++)
#pragma unroll
                for (int o = 0; o < 8; o++) fma2(acc2[q][o], vv[q+kx], wv[o]);
            }
        }
        __syncthreads();
    }
    int oy = oy0 + ty;
    float bb[16];
#pragma unroll
    for (int i = 0; i < 16; i++) bb[i] = b[tz*16+i];
#pragma unroll
    for (int q = 0; q < 4; q++) {
        float* zp = g_z + (((size_t)n*64+oy)*64 + ox0+tx*4+q)*64 + tz*16;
#pragma unroll
        for (int o = 0; o < 8; o++) {
            float2 e = unpk(acc2[q][o]);
            float2 r; r.x = e.x + bb[2*o]; r.y = e.y + bb[2*o+1];
            ((float2*)zp)[o] = r;
        }
    }
}

__global__ void k_ee(const float* __restrict__ emb) {
    int k = threadIdx.x;
    float s = 0.f;
    for (int d = 0; d < 64; d++) { float e = emb[d*512+k]; s += e*e; }
    g_ee[k] = s;
}

__global__ void __launch_bounds__(256) k_vq(const float* __restrict__ emb) {
    __shared__ float sE[64*68];
    __shared__ float sEE[64];
    int tid = threadIdx.x;
    int row = blockIdx.x*256 + tid;
    u64 zr2[32];
    const float4* zp = (const float4*)(g_z + (size_t)row*64);
#pragma unroll
    for (int j = 0; j < 16; j++) { float4 t = zp[j]; zr2[2*j] = pk(t.x,t.y); zr2[2*j+1] = pk(t.z,t.w); }
    float best = 3.4e38f;
    int bi = 0;
    for (int kc = 0; kc < 512; kc += 64) {
        __syncthreads();
        for (int i = tid; i < 4096; i += 256) { int d = i>>6, k = i&63; sE[k*68+d] = emb[d*512+kc+k]; }
        if (tid < 64) sEE[tid] = g_ee[kc+tid];
        __syncthreads();
        for (int k = 0; k < 64; k++) {
            const ulonglong2* ep = (const ulonglong2*)&sE[k*68];
            u64 sa = 0ull, sb = 0ull;
#pragma unroll
            for (int jj = 0; jj < 16; jj++) { ulonglong2 e = ep[jj]; fma2(sa, zr2[2*jj], e.x); fma2(sb, zr2[2*jj+1], e.y); }
            float2 fa = unpk(sa), fb = unpk(sb);
            float dd = sEE[k] - 2.f*((fa.x+fa.y)+(fb.x+fb.y));
            if (dd < best) { best = dd; bi = kc + k; }
        }
    }
    g_idx[row] = bi;
    atomicAdd(&g_counts[bi], 1.f);
}

__global__ void __launch_bounds__(256) k_gather(const float* __restrict__ emb) {
    __shared__ float sQ[8192];
    __shared__ float sRed[256];
    int tid = threadIdx.x;
    int r0 = blockIdx.x*128;
    int rl = tid & 127, half = tid >> 7;
    int r = r0 + rl;
    int id = g_idx[r];
    const float4* z4 = (const float4*)(g_z + (size_t)r*64 + half*32);
    float ls = 0.f;
#pragma unroll
    for (int jj = 0; jj < 8; jj++) {
        float4 zv = z4[jj];
        int d = half*32 + jj*4;
        float e0 = emb[(d+0)*512+id], e1 = emb[(d+1)*512+id], e2 = emb[(d+2)*512+id], e3 = emb[(d+3)*512+id];
        float d0 = e0-zv.x, d1 = e1-zv.y, d2 = e2-zv.z, d3 = e3-zv.w;
        ls += d0*d0 + d1*d1 + d2*d2 + d3*d3;
        sQ[(d+0)*128+rl] = e0; sQ[(d+1)*128+rl] = e1; sQ[(d+2)*128+rl] = e2; sQ[(d+3)*128+rl] = e3;
    }
    __syncthreads();
    int n = r0 >> 12;
    float* qb = g_q + ((size_t)n << 18) + (r0 & 4095);
    for (int i = tid; i < 8192; i += 256) qb[(size_t)(i>>7)*4096 + (i&127)] = sQ[i];
    sRed[tid] = ls;
    __syncthreads();
    for (int s = 128; s > 0; s >>= 1) { if (tid < s) sRed[tid] += sRed[tid+s]; __syncthreads(); }
    if (tid == 0) atomicAdd(&g_loss_sum, (double)sRed[0]);
}

__global__ void k_finalize(float* __restrict__ out, int out_size) {
    __shared__ float red[512];
    int t = threadIdx.x;
    float p = g_counts[t] * (1.f/131072.f);
    red[t] = p * logf(p + 1e-10f);
    __syncthreads();
    for (int s = 256; s > 0; s >>= 1) { if (t < s) red[t] += red[t+s]; __syncthreads(); }
    if (t == 0) { out[out_size-1] = expf(-red[0]); out[0] = (float)(g_loss_sum * (1.25/8388608.0)); }
}

__global__ void k_repack(const float* __restrict__ w, unsigned short* __restrict__ dst,
                         int C, int ICC, int OCt) {
    int idx = blockIdx.x*256 + threadIdx.x;
    int k = idx & 63, n = (idx >> 6) & 127, part = (idx >> 13) & 1, rest = idx >> 14;
    int c = rest % C, h = rest / C;
    int dy = n >> 6, ocl = n & 63, dx = h & 1, och = h >> 1;
    int tap = c / ICC, icc = c - tap*ICC;
    int ty = tap >> 1, txx = tap & 1;
    int ky = dy - 2*ty + 1, kx = dx - 2*txx + 1;
    int ic = icc*64 + k, oc = och*64 + ocl;
    float v = (ky >= 0 && kx >= 0) ? w[((size_t)ic*OCt + oc)*9 + ky*3 + kx] : 0.f;
    __nv_bfloat16 hh = __float2bfloat16(v);
    unsigned short bits = (part == 0) ? __bfloat16_as_ushort(hh)
        : __bfloat16_as_ushort(__float2bfloat16(v - __bfloat162float(hh)));
    dst[(size_t)((h*C + c)*2 + part)*8192 + n*64 + ((((unsigned)k>>3) ^ (n&7))<<3) + (k&7)] = bits;
}

// pipelined mma.sync transposed conv: M=128 x N=128 x K=64/chunk, 3-pass bf16,
// A double-buffered via register prefetch, B double-buffered via cp.async.
template<int INS, int IC, int OC>
__global__ void __launch_bounds__(256) k_convT_mma(const float* __restrict__ in,
    const unsigned short* __restrict__ wb, const float* __restrict__ bias, float* __restrict__ out) {
    constexpr int ICC = IC/64, C = 4*ICC, XW = INS, ROWS = 128/XW, OUTS = 2*INS;
    constexpr int LOGXW = (INS == 64) ? 6 : 7;
    extern __shared__ char smg[];
    uint32_t sb = saddr(smg);            // A: buf*32768 (hi 0, lo +16384); B at 65536 + buf*32768
    float* sBias = (float*)(smg + 131072);
    int tid = threadIdx.x, lane = tid & 31, wid = tid >> 5;
    int y0 = blockIdx.x*ROWS, nb = blockIdx.y, h = blockIdx.z;
    int dx = h & 1, och = h >> 1;
    int m0w = (wid >> 1) * 32, n0w = (wid & 1) * 64;
    const float* inb = in + (size_t)nb*IC*INS*INS;
    if (tid < 64) sBias[tid] = bias[och*64 + tid];
    float acc[2][8][4];
#pragma unroll
    for (int i = 0; i < 2; i++)
#pragma unroll
    for (int j = 0; j < 8; j++)
#pragma unroll
    for (int q = 0; q < 4; q++) acc[i][j][q] = 0.f;
    int kbase = wid * 8;

    auto a_load = [&](int c, float* vA) {
        int tap = c / ICC, icc = c - tap*ICC;
        int tty = tap >> 1, ttx = tap & 1;
#pragma unroll
        for (int kk2 = 0; kk2 < 4; kk2++) {
            int k = kbase + kk2*2;
            const float* s0 = inb + (size_t)(icc*64 + k)*INS*INS;
            const float* s1 = s0 + (size_t)INS*INS;
#pragma unroll
            for (int mb = 0; mb < 4; mb++) {
                int m = mb*32 + lane;
                int rr = m >> LOGXW, x = m & (XW-1);
                int y = y0 + rr + tty, xx = x + ttx;
                bool ok = (y < INS) && (xx < INS);
                size_t off = (size_t)y*INS + xx;
                vA[(kk2*4+mb)*2+0] = ok ? s0[off] : 0.f;
                vA[(kk2*4+mb)*2+1] = ok ? s1[off] : 0.f;
            }
        }
    };
    auto a_store = [&](const float* vA, uint32_t Ab) {
#pragma unroll
        for (int kk2 = 0; kk2 < 4; kk2++) {
            int k = kbase + kk2*2;
#pragma unroll
            for (int mb = 0; mb < 4; mb++) {
                int m = mb*32 + lane;
                float v0 = vA[(kk2*4+mb)*2+0], v1 = vA[(kk2*4+mb)*2+1];
                float h0 = __bfloat162float(__float2bfloat16(v0));
                float h1 = __bfloat162float(__float2bfloat16(v1));
                uint32_t wofs = (uint32_t)m*128 + ((((unsigned)k>>3) ^ (m&7))<<4) + (k&7)*2;
                uint32_t hw, lw;
                asm("cvt.rn.bf16x2.f32 %0, %1, %2;" : "=r"(hw) : "f"(v1), "f"(v0));
                asm("cvt.rn.bf16x2.f32 %0, %1, %2;" : "=r"(lw) : "f"(v1-h1), "f"(v0-h0));
                st32(Ab + wofs, hw);
                st32(Ab + 16384 + wofs, lw);
            }
        }
    };
    auto b_fill = [&](int c, uint32_t Bb) {
        for (int i = tid; i < 2048; i += 256) {
            int part = i >> 10, wi = i & 1023;
            cp16(Bb + part*16384 + wi*16,
                 wb + (size_t)((h*C + c)*2 + part)*8192 + wi*8);
        }
    };

    float vA[32];
    a_load(0, vA);
    b_fill(0, sb + 65536); cp_commit();
    a_store(vA, sb);
    cp_wait0();
    __syncthreads();

    for (int c = 0; c < C; c++) {
        int buf = c & 1;
        uint32_t Abase = sb + buf*32768;
        uint32_t Bbase = sb + 65536 + buf*32768;
        if (c + 1 < C) {
            a_load(c+1, vA);                       // LDGs in flight during compute
            b_fill(c+1, sb + 65536 + (buf^1)*32768);
            cp_commit();
        }
#pragma unroll
        for (int pass = 0; pass < 3; pass++) {
            uint32_t Ab = Abase + ((pass == 2) ? 16384 : 0);
            uint32_t Bb = Bbase + ((pass == 1) ? 16384 : 0);
#pragma unroll
            for (int ks = 0; ks < 4; ks++) {
                int lrow = lane & 15, lcol = lane >> 4;
                uint32_t a[2][4], bq[4][4];
#pragma unroll
                for (int mi = 0; mi < 2; mi++) {
                    int rw = m0w + mi*16 + lrow;
                    ldsm4(a[mi], Ab + (uint32_t)rw*128 + ((((unsigned)(ks*2+lcol)) ^ (rw&7))<<4));
                }
#pragma unroll
                for (int nq = 0; nq < 4; nq++) {
                    int rw = n0w + nq*16 + lrow;
                    ldsm4(bq[nq], Bb + (uint32_t)rw*128 + ((((unsigned)(ks*2+lcol)) ^ (rw&7))<<4));
                }
#pragma unroll
                for (int mi = 0; mi < 2; mi++)
#pragma unroll
                for (int nj = 0; nj < 8; nj++)
                    mma16816(acc[mi][nj], a[mi], bq[nj>>1][nj&1], bq[nj>>1][(nj&1)+2]);
            }
        }
        if (c + 1 < C) {
            a_store(vA, sb + (buf^1)*32768);
            cp_wait0();
        }
        __syncthreads();
    }
    // epilogue
    int grow = lane >> 2, gcol = (lane & 3)*2;
#pragma unroll
    for (int mi = 0; mi < 2; mi++)
#pragma unroll
    for (int rg2 = 0; rg2 < 2; rg2++) {
        int m = m0w + mi*16 + grow + rg2*8;
        int rr = m >> LOGXW, x = m & (XW-1);
        int ox = 2*x + dx;
        int oyb = 2*(y0 + rr);
#pragma unroll
        for (int nj = 0; nj < 8; nj++)
#pragma unroll
        for (int cc = 0; cc < 2; cc++) {
            int n = n0w + nj*8 + gcol + cc;
            int dy = n >> 6, ocl = n & 63;
            float v = fmaxf(acc[mi][nj][rg2*2 + cc] + sBias[ocl], 0.f);
            out[(((size_t)nb*OC + och*64 + ocl)*OUTS + oyb + dy)*OUTS + ox] = v;
        }
    }
}

__global__ void __launch_bounds__(256) k_convT3(const float* __restrict__ w,
                                                const float* __restrict__ b,
                                                float* __restrict__ out) {
    extern __shared__ float smT[];
    float* sInD = smT;
    float* sW   = smT + 2*9504;
    int tid = threadIdx.x, tx = tid & 15, ty = tid >> 4;
    int n = blockIdx.z, y0 = blockIdx.y*16, x0 = blockIdx.x*64;
    for (int i = tid; i < 576; i += 256) { int ic = i/9, t = i - ic*9; sW[i] = w[ic*9 + (8-t)]; }
    u64 acc2[2] = {};
    const float* inb = g_g2 + (size_t)n * 64 * 65536;
    auto fill = [&](int ic0, int buf) {
        float* dI = sInD + buf*9504;
        for (int i = tid; i < 9504; i += 256) {
            int j = i/1188, rem = i - j*1188, yy = rem/66, xx = rem - yy*66;
            int iy = y0-1+yy, ix = x0-1+xx;
            bool pr = (iy >= 0 && iy < 256 && ix >= 0 && ix < 256);
            cp4(saddr(dI+i), pr ? &inb[(size_t)(ic0+j)*65536 + (size_t)iy*256 + ix] : inb, pr);
        }
    };
    fill(0, 0); cp_commit();
    for (int c = 0; c < 8; c++) {
        int buf = c & 1;
        if (c+1 < 8) fill((c+1)*8, (c+1)&1);
        cp_commit(); cp_wait1(); __syncthreads();
        const float* pI = sInD + buf*9504;
        int ic0 = c*8;
#pragma unroll
        for (int j = 0; j < 8; j++) {
            u64 wr2[9];
#pragma unroll
            for (int t = 0; t < 9; t++) { float t0 = sW[(ic0+j)*9+t]; wr2[t] = pk(t0,t0); }
#pragma unroll
            for (int a = 0; a < 3; a++) {
                const float* rp = &pI[(j*18+ty+a)*66+tx*4];
                float v[6];
#pragma unroll
                for (int cc = 0; cc < 6; cc++) v[cc] = rp[cc];
                u64 pv[5];
#pragma unroll
                for (int cc = 0; cc < 5; cc++) pv[cc] = pk(v[cc], v[cc+1]);
#pragma unroll
                for (int bb = 0; bb < 3; bb++) { fma2(acc2[0], pv[bb], wr2[a*3+bb]); fma2(acc2[1], pv[bb+2], wr2[a*3+bb]); }
            }
        }
        __syncthreads();
    }
    float bias = b[0];
    float* ob = out + (size_t)n*65536 + (size_t)(y0+ty)*256 + x0 + tx*4;
    float2 f0 = unpk(acc2[0]), f1 = unpk(acc2[1]);
    ob[0] = f0.x + bias; ob[1] = f0.y + bias; ob[2] = f1.x + bias; ob[3] = f1.y + bias;
}

extern "C" void kernel_launch(void* const* d_in, const int* in_sizes, int n_in,
                              void* d_out, int out_size) {
    const float* x   = (const float*)d_in[0];
    const float* ew1 = (const float*)d_in[1];
    const float* eb1 = (const float*)d_in[2];
    const float* ew2 = (const float*)d_in[3];
    const float* eb2 = (const float*)d_in[4];
    const float* ew3 = (const float*)d_in[5];
    const float* eb3 = (const float*)d_in[6];
    const float* emb = (const float*)d_in[7];
    const float* dw1 = (const float*)d_in[8];
    const float* db1 = (const float*)d_in[9];
    const float* dw2 = (const float*)d_in[10];
    const float* db2 = (const float*)d_in[11];
    const float* dw3 = (const float*)d_in[12];
    const float* db3 = (const float*)d_in[13];
    float* out = (float*)d_out;

    float *pq, *pg1, *pg2;
    unsigned short *pw1, *pw2;
    cudaGetSymbolAddress((void**)&pq,  g_q);
    cudaGetSymbolAddress((void**)&pg1, g_g1);
    cudaGetSymbolAddress((void**)&pg2, g_g2);
    cudaGetSymbolAddress((void**)&pw1, g_wb1);
    cudaGetSymbolAddress((void**)&pw2, g_wb2);

    const int smem2 = (2*4752 + 2*4096)*4;
    const int smem3 = (2*2720 + 2*4608)*4;
    const int smemT3 = (2*9504 + 576)*4;
    const int smemM = 131072 + 256;
    cudaFuncSetAttribute(k_conv2, cudaFuncAttributeMaxDynamicSharedMemorySize, smem2);
    cudaFuncSetAttribute(k_conv3, cudaFuncAttributeMaxDynamicSharedMemorySize, smem3);
    cudaFuncSetAttribute(k_convT3, cudaFuncAttributeMaxDynamicSharedMemorySize, smemT3);
    cudaFuncSetAttribute(k_convT_mma<64,64,128>,  cudaFuncAttributeMaxDynamicSharedMemorySize, smemM);
    cudaFuncSetAttribute(k_convT_mma<128,128,64>, cudaFuncAttributeMaxDynamicSharedMemorySize, smemM);

    k_init<<<1, 512>>>();
    k_repack<<<1024, 256>>>(dw1, pw1, 4, 1, 128);
    k_repack<<<1024, 256>>>(dw2, pw2, 8, 2, 64);
    k_conv1<<<dim3(128, 32), 128>>>(x, ew1, eb1);
    k_conv2<<<dim3(2, 8, 32), 256, smem2>>>(ew2, eb2);
    k_conv3<<<dim3(2, 8, 32), 256, smem3>>>(ew3, eb3);
    k_ee<<<1, 512>>>(emb);
    k_vq<<<512, 256>>>(emb);
    k_gather<<<1024, 256>>>(emb);
    k_convT_mma<64,64,128><<<dim3(32, 32, 4), 256, smemM>>>(pq, pw1, db1, pg1);
    k_convT_mma<128,128,64><<<dim3(128, 32, 2), 256, smemM>>>(pg1, pw2, db2, pg2);
    k_convT3<<<dim3(4, 16, 32), 256, smemT3>>>(dw3, db3, out + 1);
    k_finalize<<<1, 512>>>(out, out_size);
}